// round 2
// baseline (speedup 1.0000x reference)
#include <cuda_runtime.h>
#include <float.h>
#include <stdint.h>

// Fixed problem shape
#define KC   512            // codebook size
#define DC   64             // code dim
#define HWC  4096           // H*W
#define NC   131072         // B*H*W
#define TPB  256
#define ETS  520            // padded row stride for transposed codebook (floats)

// smem floats: ET[64][520] + enorm[512] + red[256]
#define ET_FLOATS   (DC * ETS)
#define SMEM_FLOATS (ET_FLOATS + KC + TPB)
#define SMEM_BYTES  (SMEM_FLOATS * 4)

__device__ float g_loss_sum;

__device__ __forceinline__ float2 ffma2(float2 a, float2 b, float2 c) {
    unsigned long long ra = *reinterpret_cast<unsigned long long*>(&a);
    unsigned long long rb = *reinterpret_cast<unsigned long long*>(&b);
    unsigned long long rc = *reinterpret_cast<unsigned long long*>(&c);
    unsigned long long rd;
    asm("fma.rn.f32x2 %0, %1, %2, %3;" : "=l"(rd) : "l"(ra), "l"(rb), "l"(rc));
    return *reinterpret_cast<float2*>(&rd);
}

__global__ void vq_zero() {
    g_loss_sum = 0.0f;
}

__global__ void vq_finalize(float* loss_out) {
    // m = mean((q-lat)^2); division by 2^23 elements is exact
    float m = g_loss_sum / 8388608.0f;
    // vq_loss = fl( fl(0.25*m) + m )   (commitment*BETA + embedding_loss, identical arrays)
    *loss_out = __fadd_rn(__fmul_rn(m, 0.25f), m);
}

__global__ __launch_bounds__(TPB)
void vq_kernel(const float* __restrict__ latents,
               const float* __restrict__ embedding,
               float* __restrict__ out) {
    extern __shared__ float smem[];
    float* ET    = smem;                 // [64][520], ET[d*ETS + k]
    float* eNorm = smem + ET_FLOATS;     // [512]
    float* red   = eNorm + KC;           // [256]

    const int tid = threadIdx.x;

    // ---- stage transposed codebook (coalesced gmem read, scattered STS) ----
    {
        const float4* src = reinterpret_cast<const float4*>(embedding);
        #pragma unroll
        for (int i4 = tid; i4 < (KC * DC) / 4; i4 += TPB) {
            float4 v = src[i4];
            int i = i4 * 4;
            int k = i >> 6;        // i / 64
            int d = i & 63;        // i % 64  (float4 never crosses a row: 64%4==0)
            ET[(d + 0) * ETS + k] = v.x;
            ET[(d + 1) * ETS + k] = v.y;
            ET[(d + 2) * ETS + k] = v.z;
            ET[(d + 3) * ETS + k] = v.w;
        }
    }
    __syncthreads();

    // ---- enorm_k: sequential d, separate mul/add rounding (XLA reduce emulation) ----
    #pragma unroll
    for (int k = tid; k < KC; k += TPB) {
        float s = 0.0f;
        #pragma unroll
        for (int d = 0; d < DC; ++d) {
            float e = ET[d * ETS + k];
            s = __fadd_rn(s, __fmul_rn(e, e));
        }
        eNorm[k] = s;
    }
    __syncthreads();

    // ---- this thread's pixel ----
    const int p  = blockIdx.x * TPB + tid;
    const int b  = p >> 12;
    const int hw = p & (HWC - 1);
    const float* lat = latents + (size_t)b * DC * HWC + hw;

    float f[DC];
    #pragma unroll
    for (int d = 0; d < DC; ++d) f[d] = lat[d * HWC];

    // fnorm: sequential d, separate mul/add
    float fnorm = 0.0f;
    #pragma unroll
    for (int d = 0; d < DC; ++d) fnorm = __fadd_rn(fnorm, __fmul_rn(f[d], f[d]));

    // ---- argmin: dist_k = fl( fl(fnorm + enorm_k) - fl(2*dot_k) ) ----
    // dot_k = sequential FMA chain over d (Eigen GEMM emulation), one chain per
    // f32x2 lane so pairing codes preserves bit-exactness.
    float best  = FLT_MAX;
    int   bestk = 0;

    #pragma unroll 1
    for (int k0 = 0; k0 < KC; k0 += 16) {
        float2 a0 = {0.f,0.f}, a1 = {0.f,0.f}, a2 = {0.f,0.f}, a3 = {0.f,0.f};
        float2 a4 = {0.f,0.f}, a5 = {0.f,0.f}, a6 = {0.f,0.f}, a7 = {0.f,0.f};

        #pragma unroll 8
        for (int d = 0; d < DC; ++d) {
            float fd = f[d];
            float2 f2; f2.x = fd; f2.y = fd;
            const float4* row4 = reinterpret_cast<const float4*>(ET + d * ETS + k0);
            float4 e0 = row4[0];
            float4 e1 = row4[1];
            float4 e2 = row4[2];
            float4 e3 = row4[3];
            a0 = ffma2(f2, make_float2(e0.x, e0.y), a0);
            a1 = ffma2(f2, make_float2(e0.z, e0.w), a1);
            a2 = ffma2(f2, make_float2(e1.x, e1.y), a2);
            a3 = ffma2(f2, make_float2(e1.z, e1.w), a3);
            a4 = ffma2(f2, make_float2(e2.x, e2.y), a4);
            a5 = ffma2(f2, make_float2(e2.z, e2.w), a5);
            a6 = ffma2(f2, make_float2(e3.x, e3.y), a6);
            a7 = ffma2(f2, make_float2(e3.z, e3.w), a7);
        }

        float dots[16] = {a0.x,a0.y,a1.x,a1.y,a2.x,a2.y,a3.x,a3.y,
                          a4.x,a4.y,a5.x,a5.y,a6.x,a6.y,a7.x,a7.y};
        #pragma unroll
        for (int j = 0; j < 16; ++j) {
            int k = k0 + j;
            float t = __fadd_rn(fnorm, eNorm[k]);     // fnorm + enorm  (rounded)
            float u = __fmul_rn(2.0f, dots[j]);       // 2*dot          (rounded/exact)
            float s = __fsub_rn(t, u);                // dist           (rounded)
            if (s < best) { best = s; bestk = k; }    // strict < => first-min
        }
    }

    // ---- epilogue: gather code, STE output, per-pixel loss partial ----
    float* outp = out + (size_t)b * DC * HWC + hw;
    float ldist = 0.0f;
    #pragma unroll
    for (int d = 0; d < DC; ++d) {
        float q  = ET[d * ETS + bestk];
        float fd = f[d];
        float dq = __fsub_rn(q, fd);                  // (q - lat)   rounded
        ldist = __fadd_rn(ldist, __fmul_rn(dq, dq));  // (q-lat)^2 accumulated
        outp[d * HWC] = __fadd_rn(fd, dq);            // lat + (q - lat)  (STE rounding)
    }

    // ---- block reduce loss, one atomic per block ----
    red[tid] = ldist;
    __syncthreads();
    #pragma unroll
    for (int s = TPB / 2; s > 0; s >>= 1) {
        if (tid < s) red[tid] += red[tid + s];
        __syncthreads();
    }
    if (tid == 0) atomicAdd(&g_loss_sum, red[0]);
}

extern "C" void kernel_launch(void* const* d_in, const int* in_sizes, int n_in,
                              void* d_out, int out_size) {
    const float* latents   = (const float*)d_in[0];   // [32, 64, 64, 64] fp32
    const float* embedding = (const float*)d_in[1];   // [512, 64] fp32
    float* out  = (float*)d_out;                      // tensor [32,64,64,64], then loss
    float* loss = out + (out_size - 1);

    cudaFuncSetAttribute(vq_kernel, cudaFuncAttributeMaxDynamicSharedMemorySize, SMEM_BYTES);

    vq_zero<<<1, 1>>>();
    vq_kernel<<<NC / TPB, TPB, SMEM_BYTES>>>(latents, embedding, out);
    vq_finalize<<<1, 1>>>(loss);
}